// round 16
// baseline (speedup 1.0000x reference)
#include <cuda_runtime.h>
#include <math.h>
#include <stdint.h>

#define B 8
#define UP 8
#define A 32
#define L 3264
#define H 256
#define BSZ 12
#define KCS 12
#define ND 61
#define NPT (UP*ND)        /* 488 */
#define L4 (L/4)           /* 816 */
#define NM (B*UP)          /* 64 */
#define M2L (2*L)          /* 6528 */
#define NOUT 576
#define GK1 34
#define GKLEN (M2L/GK1)    /* 192 */
#define F1 272             /* L = 272 * 12 */
#define F2 12
#define NSP 8              /* n-segments of fused havg+resen */
#define NSEG 408           /* n per segment */
#define DSPLIT 2           /* bin-splits of k_dft */
#define BINS_PER (NPT/DSPLIT)  /* 244 */
#define FCH 1632           /* k_final chunk (divisible by 12) */

// ---------------- scratch (static device globals; no allocation) ----------------
__device__ float2 d_S[B*A][NPT];
__device__ int    d_toff[NM];
__device__ float  d_m[NM];
__device__ float2 d_phm[NM*L];
__device__ float2 d_phT[NM*L];
__device__ float2 d_havg[NM*A*L4];
__device__ float2 d_res[B*A*L];
__device__ float  d_epart[NSP][NM*A];
__device__ float  d_feat[NM*M2L];
__device__ float  d_h1pre[GK1][NM][H];
__device__ float2 d_wm[NM*BSZ*BSZ];

// exact 12th roots of unity
__device__ __constant__ float C12[12] = {
    1.0f,  0.86602540378443864676f,  0.5f, 0.0f, -0.5f, -0.86602540378443864676f,
   -1.0f, -0.86602540378443864676f, -0.5f, 0.0f,  0.5f,  0.86602540378443864676f };
__device__ __constant__ float S12[12] = {
    0.0f,  0.5f,  0.86602540378443864676f, 1.0f,  0.86602540378443864676f,  0.5f,
    0.0f, -0.5f, -0.86602540378443864676f,-1.0f, -0.86602540378443864676f, -0.5f };

// ---------------- K1: fused radix-12 fold + candidate-bin DFT ----------------
// grid (B*A, DSPLIT), block 512. Stage B: two threads per bin (k-parity split).
__global__ void k_dft(const float* __restrict__ lr, const float* __restrict__ li,
                      const int* __restrict__ cs) {
    __shared__ float2 sU[F2][F1+1];   // 26 KB, pad 273
    int ba = blockIdx.x, halfb = blockIdx.y, t = threadIdx.x;
    if (t < F1) {
        int k1 = t;
        const float* xr = lr + ba*L;
        const float* xi = li + ba*L;
        float vr[F2], vi[F2];
        #pragma unroll
        for (int k2 = 0; k2 < F2; k2++) {
            vr[k2] = xr[k1 + F1*k2];
            vi[k2] = xi[k1 + F1*k2];
        }
        #pragma unroll
        for (int rho = 0; rho < F2; rho++) {
            float ur = 0.f, ui = 0.f;
            #pragma unroll
            for (int k2 = 0; k2 < F2; k2++) {
                float c = C12[(rho*k2) % 12], s = S12[(rho*k2) % 12];
                ur += vr[k2]*c - vi[k2]*s;
                ui += vr[k2]*s + vi[k2]*c;
            }
            sU[rho][k1] = make_float2(ur, ui);
        }
    }
    __syncthreads();
    bool active = (t < 2*BINS_PER);
    int p = active ? (halfb*BINS_PER + (t >> 1)) : (halfb*BINS_PER);
    int parity = t & 1;
    int up = p / ND, dd = p - up*ND;
    int ip = ((KCS - cs[up]) % KCS) * (L / KCS);
    int n = (ip + dd - 30 + L) % L;
    int rho = n % F2;
    const double w0 = 6.283185307179586476925286766559 / (double)L;
    float w2x, w2y;
    { int r2 = (2*n) % L; float th = (float)(w0 * (double)r2); sincosf(th, &w2y, &w2x); }
    float Sx = 0.f, Sy = 0.f;
    #pragma unroll
    for (int m0 = 0; m0 < 136; m0 += 68) {    // resync every 68 pair-steps
        long long k1s = 2*m0 + parity;
        int r = (int)((k1s * (long long)n) % (long long)L);
        float zx, zy;
        { float th = (float)(w0 * (double)r); sincosf(th, &zy, &zx); }
        #pragma unroll 4
        for (int m = m0; m < m0 + 68; m++) {
            float2 u = sU[rho][2*m + parity];
            Sx += u.x*zx - u.y*zy;
            Sy += u.x*zy + u.y*zx;
            float nzx = zx*w2x - zy*w2y;
            float nzy = zx*w2y + zy*w2x;
            zx = nzx; zy = nzy;
        }
    }
    Sx += __shfl_xor_sync(0xffffffffu, Sx, 1);
    Sy += __shfl_xor_sync(0xffffffffu, Sy, 1);
    if (active && parity == 0) d_S[ba][p] = make_float2(Sx, Sy);
}

// ---------------- K2: power reduce over a + argmax over d ----------------
__global__ void k_peak(const int* __restrict__ cs) {
    __shared__ float sp[ND];
    int up = blockIdx.x, b = blockIdx.y;
    int tid = threadIdx.x;
    if (tid < ND) {
        int pt = up*ND + tid;
        float s = 0.f;
        for (int a = 0; a < A; a++) {
            float2 v = d_S[b*A + a][pt];
            s += v.x*v.x + v.y*v.y;
        }
        sp[tid] = s;
    }
    __syncthreads();
    if (tid == 0) {
        float best = sp[0]; int bd = 0;
        for (int i = 1; i < ND; i++) if (sp[i] > best) { best = sp[i]; bd = i; }
        int toff = bd - 30;
        int ipk = ((KCS - cs[up]) % KCS) * (L / KCS);
        d_toff[b*UP + up] = toff;
        d_m[b*UP + up]    = (float)(toff + ipk);
    }
}

// accurate sin/cos of a (possibly huge) fp32 phase: double range reduction.
__device__ __forceinline__ float2 expi_big(float th) {
    const double TWO_PI = 6.283185307179586476925286766559;
    const double INV_TWO_PI = 0.15915494309189533576888376337251;
    double x = (double)th;
    double r = x - TWO_PI * rint(x * INV_TWO_PI);
    float2 e; sincosf((float)r, &e.y, &e.x);
    return e;
}

// ---------------- K3: phasor tables (reproduce reference fp32 phase exactly) ----
__global__ void k_phasor() {
    int i = blockIdx.x * blockDim.x + threadIdx.x;   // exactly NM*L
    int bu = i / L, n = i - bu*L;
    const float W = (float)(6.283185307179586476925286766559 / (double)L);
    float nf = (float)n;
    float wm = W * d_m[bu];
    d_phm[i] = expi_big(wm * nf);
    float wt = W * (float)d_toff[bu];
    d_phT[i] = expi_big(wt * nf);
}

// ---------------- K4: fused h_avg + residual + partial energies ----------------
// NSP=8 segments of 408 n. Stage 1 (row-per-thread, ups in registers) computes
// havg rows AND stashes the phasor quads it already loaded into sP, so stage 2
// reads phasors from smem. Energy: |h_res|^2 = |c + res|^2, c = hi*conj(ph).
__global__ void k_havgres(const float* __restrict__ lr, const float* __restrict__ li) {
    __shared__ float2 sH[UP][105];
    __shared__ float2 sP[UP][416];   // phm[n] at index n - n_lo + 4
    __shared__ float sE[8][9];
    int s  = blockIdx.x;
    int ba = blockIdx.y; int a = ba % A; int b = ba / A;
    int t = threadIdx.x;
    int n_lo = s * NSEG, n_hi = n_lo + NSEG;
    int j_lo = (s == 0) ? 0 : 102*s - 1;
    int j_hi = min(815, 102*s + 102);
    int nrows = j_hi - j_lo + 1;    // <= 104

    // ---- stage 1: havg rows + phasor stash ----
    if (t < nrows) {
        int j = j_lo + t;
        const float4* lr4 = (const float4*)lr;
        const float4* li4 = (const float4*)li;
        float4 xr = lr4[(b*A + a)*L4 + j];
        float4 xi = li4[(b*A + a)*L4 + j];
        int pidx = 4*j - n_lo + 4;
        #pragma unroll
        for (int up = 0; up < UP; up++) {
            int bu = b*UP + up;
            const float4* ph4 = (const float4*)&d_phm[bu*L + 4*j];
            float4 p01 = ph4[0], p23 = ph4[1];
            sP[up][pidx+0] = make_float2(p01.x, p01.y);
            sP[up][pidx+1] = make_float2(p01.z, p01.w);
            sP[up][pidx+2] = make_float2(p23.x, p23.y);
            sP[up][pidx+3] = make_float2(p23.z, p23.w);
            float sx, sy;
            sx  = xr.x*p01.x - xi.x*p01.y;  sy  = xr.x*p01.y + xi.x*p01.x;
            sx += xr.y*p01.z - xi.y*p01.w;  sy += xr.y*p01.w + xi.y*p01.z;
            sx += xr.z*p23.x - xi.z*p23.y;  sy += xr.z*p23.y + xi.z*p23.x;
            sx += xr.w*p23.z - xi.w*p23.w;  sy += xr.w*p23.w + xi.w*p23.z;
            float2 hv = make_float2(sx*0.25f, sy*0.25f);
            sH[up][t] = hv;
            d_havg[(bu*A + a)*L4 + j] = hv;
        }
    }
    __syncthreads();

    // ---- stage 2: residual + energies, n-contiguous, phasors from smem ----
    float en[UP];
    #pragma unroll
    for (int up = 0; up < UP; up++) en[up] = 0.f;
    int base = (b*A + a)*L;

    for (int n = n_lo + t; n < n_hi; n += 256) {
        int j = (n < 2) ? 0 : ((n >= L-2) ? 815 : (n-2) >> 2);
        float tq = (n < 2 || n >= L-2) ? 0.f : 0.125f + 0.25f*(float)((n-2) & 3);
        int r0 = j - j_lo;
        int r1 = r0 + (j < 815 ? 1 : 0);
        int pidx = n - n_lo + 4;
        float ax = lr[base + n], ay = li[base + n];
        float cx[UP], cy[UP];
        #pragma unroll
        for (int up = 0; up < UP; up++) {
            float2 v0 = sH[up][r0], v1 = sH[up][r1];
            float hx = v0.x + tq*(v1.x - v0.x);
            float hy = v0.y + tq*(v1.y - v0.y);
            float2 ph = sP[up][pidx];
            cx[up] = hx*ph.x + hy*ph.y;    // Re(hi*conj(ph))
            cy[up] = hy*ph.x - hx*ph.y;    // Im(hi*conj(ph))
            ax -= cx[up];
            ay -= cy[up];
        }
        d_res[base + n] = make_float2(ax, ay);
        #pragma unroll
        for (int up = 0; up < UP; up++) {
            float dx = cx[up] + ax, dy = cy[up] + ay;
            en[up] += dx*dx + dy*dy;
        }
    }
    #pragma unroll
    for (int up = 0; up < UP; up++) {
        float sv = en[up];
        #pragma unroll
        for (int o = 16; o; o >>= 1) sv += __shfl_down_sync(0xffffffffu, sv, o);
        if ((t & 31) == 0) sE[t >> 5][up] = sv;
    }
    __syncthreads();
    if (t < UP) {
        float tot = 0.f;
        #pragma unroll
        for (int w = 0; w < 8; w++) tot += sE[w][t];
        d_epart[s][(b*UP + t)*A + a] = tot;
    }
}

// linear interp on the LOCC grid (matches jnp.interp incl. edge clamping)
__device__ __forceinline__ float2 hinterp(int bu, int a, int n) {
    const float2* row = &d_havg[(bu*A + a)*L4];
    if (n < 2)     return row[0];
    if (n > L-3)   return row[L4-1];
    float x = (float)n - 1.5f;
    int j = (int)(x * 0.25f);
    float t = (x - 4.0f*(float)j) * 0.25f;
    float2 v0 = row[j], v1 = row[j+1];
    return make_float2(v0.x + t*(v1.x - v0.x), v0.y + t*(v1.y - v0.y));
}

__device__ __forceinline__ float2 hres_val(int bu, int a, int n, int b) {
    float2 hi = hinterp(bu, a, n);
    float2 rs = d_res[(b*A + a)*L + n];
    float2 ph = d_phm[bu*L + n];
    return make_float2(hi.x + rs.x*ph.x - rs.y*ph.y,
                       hi.y + rs.x*ph.y + rs.y*ph.x);
}

// ---------------- K7: reduce energy partials, argmax antenna, build features ----
__global__ void k_feat() {
    __shared__ int s_ai;
    int bu = blockIdx.x, b = bu / UP;
    int seg = blockIdx.y;
    if (threadIdx.x == 0) {
        float best = -1.f; int bi = 0;
        for (int a = 0; a < A; a++) {
            float e = 0.f;
            #pragma unroll
            for (int s = 0; s < NSP; s++) e += d_epart[s][bu*A + a];
            if (e > best) { best = e; bi = a; }
        }
        s_ai = bi;
    }
    __syncthreads();
    int a = s_ai;
    int n_lo = seg * (L/4), n_hi = n_lo + (L/4);
    for (int n = n_lo + threadIdx.x; n < n_hi; n += blockDim.x) {
        float2 h = hres_val(bu, a, n, b);
        d_feat[bu*M2L + n]     = h.x;
        d_feat[bu*M2L + L + n] = h.y;
    }
}

// ---------------- K8a: GEMM1 split-K=34  (64x6528)@(6528x256) ----------------
__global__ void k_gemm1(const float* __restrict__ W1) {
    __shared__ float sA[64][8];
    __shared__ float sB[8][64];
    int ks = blockIdx.x, nt = blockIdx.y;
    int t = threadIdx.x;
    int tx = t & 15, ty = t >> 4;
    float acc[4][4] = {};
    int k0 = ks * GKLEN;
    for (int c = 0; c < GKLEN; c += 8) {
        {
            int e = t;       int m = e >> 3, kk = e & 7;
            sA[m][kk] = d_feat[m*M2L + k0 + c + kk];
            e = t + 256;     m = e >> 3;    kk = e & 7;
            sA[m][kk] = d_feat[m*M2L + k0 + c + kk];
        }
        {
            int e = t;       int kk = e >> 6, nn = e & 63;
            sB[kk][nn] = W1[(k0 + c + kk)*H + nt*64 + nn];
            e = t + 256;     kk = e >> 6;    nn = e & 63;
            sB[kk][nn] = W1[(k0 + c + kk)*H + nt*64 + nn];
        }
        __syncthreads();
        #pragma unroll
        for (int kk = 0; kk < 8; kk++) {
            float a0 = sA[ty*4+0][kk], a1 = sA[ty*4+1][kk];
            float a2 = sA[ty*4+2][kk], a3 = sA[ty*4+3][kk];
            float b0 = sB[kk][tx*4+0], b1 = sB[kk][tx*4+1];
            float b2 = sB[kk][tx*4+2], b3 = sB[kk][tx*4+3];
            acc[0][0] += a0*b0; acc[0][1] += a0*b1; acc[0][2] += a0*b2; acc[0][3] += a0*b3;
            acc[1][0] += a1*b0; acc[1][1] += a1*b1; acc[1][2] += a1*b2; acc[1][3] += a1*b3;
            acc[2][0] += a2*b0; acc[2][1] += a2*b1; acc[2][2] += a2*b2; acc[2][3] += a2*b3;
            acc[3][0] += a3*b0; acc[3][1] += a3*b1; acc[3][2] += a3*b2; acc[3][3] += a3*b3;
        }
        __syncthreads();
    }
    #pragma unroll
    for (int r = 0; r < 4; r++)
        #pragma unroll
        for (int cc = 0; cc < 4; cc++)
            d_h1pre[ks][ty*4+r][nt*64 + tx*4+cc] = acc[r][cc];
}

// ---------------- K8b: split-K reduce + relu + GEMM2 + Wmmse (fully fused) ------
__global__ void k_mlpw(const float* __restrict__ b1,
                       const float* __restrict__ W2, const float* __restrict__ b2) {
    __shared__ float sh1[H];
    __shared__ float smlp[NOUT];
    __shared__ float2 RM[12][24];
    __shared__ float2 sAr[144];
    __shared__ float2 sCm[144];
    __shared__ float2 fvec[12];
    int m = blockIdx.x, t = threadIdx.x;   // 576 threads
    if (t < H) {
        float s = b1[t];
        #pragma unroll
        for (int ks = 0; ks < GK1; ks++) s += d_h1pre[ks][m][t];
        sh1[t] = s > 0.f ? s : 0.f;
    }
    __syncthreads();
    {
        float s = b2[t];
        #pragma unroll 4
        for (int k = 0; k < H; k++) s += sh1[k] * W2[k*NOUT + t];
        smlp[t] = s;
    }
    __syncthreads();
    if (t < 144) {
        sCm[t] = make_float2(smlp[t],       smlp[144 + t]);
        sAr[t] = make_float2(smlp[288 + t], smlp[432 + t]);
    }
    __syncthreads();
    if (t < 144) {
        int i = t / 12, j = t % 12;
        float rr = (i == j) ? 1.f : 0.f, ri = 0.f;
        #pragma unroll
        for (int k = 0; k < 12; k++) {
            float2 ax = sAr[i*12 + k], bx = sAr[j*12 + k];
            rr += ax.x*bx.x + ax.y*bx.y;
            ri += ax.y*bx.x - ax.x*bx.y;
        }
        RM[i][j]      = make_float2(rr, ri);
        RM[i][12 + j] = make_float2(i == j ? 1.f : 0.f, 0.f);
    }
    __syncthreads();
    int r = t / 24, c = t % 24;
    for (int p = 0; p < 12; p++) {
        if (t < 12) fvec[t] = RM[t][p];
        __syncthreads();
        if (t < 288 && r == p) {
            float2 pv = fvec[p];
            float den = pv.x*pv.x + pv.y*pv.y;
            float2 pinv = make_float2(pv.x/den, -pv.y/den);
            float2 v = RM[p][c];
            RM[p][c] = make_float2(v.x*pinv.x - v.y*pinv.y, v.x*pinv.y + v.y*pinv.x);
        }
        __syncthreads();
        if (t < 288 && r != p) {
            float2 f = fvec[r], pr = RM[p][c], v = RM[r][c];
            v.x -= f.x*pr.x - f.y*pr.y;
            v.y -= f.x*pr.y + f.y*pr.x;
            RM[r][c] = v;
        }
        __syncthreads();
    }
    if (t < 144) {
        int i = t / 12, j = t % 12;
        float wr = 0.f, wi = 0.f;
        #pragma unroll
        for (int k = 0; k < 12; k++) {
            float2 cm = sCm[i*12 + k], iv = RM[k][12 + j];
            wr += cm.x*iv.x - cm.y*iv.y;
            wi += cm.x*iv.y + cm.y*iv.x;
        }
        d_wm[m*144 + t] = make_float2(wr, wi);
    }
}

// ---------------- K9: Wmmse filter + derotate; 4 antennas/block share phasors --
// grid = NM * 2 * (A/4) = 1024 blocks; id = {bu:6 | ag:3 | c:1}.
__global__ void k_final(float2* __restrict__ out) {
    __shared__ float2 sW[144];
    __shared__ float2 sh[FCH];
    __shared__ float2 sphm[FCH];
    __shared__ float2 sphT[FCH];
    int id = blockIdx.x;
    int c  = id & 1;
    int ag = (id >> 1) & 7;
    int bu = id >> 4;
    int b  = bu / UP;
    int t = threadIdx.x;           // 256
    int n0 = c * FCH;
    if (t < 144) sW[t] = d_wm[bu*144 + t];
    for (int k = t; k < FCH; k += 256) {
        sphm[k] = d_phm[bu*L + n0 + k];
        sphT[k] = d_phT[bu*L + n0 + k];
    }
    __syncthreads();
    for (int ai = 0; ai < 4; ai++) {
        int a = ag*4 + ai;
        const float2* hvg = &d_havg[(bu*A + a)*L4];
        int rbase = (b*A + a)*L;
        if (ai) __syncthreads();   // WAR on sh
        for (int k = t; k < FCH; k += 256) {
            int n = n0 + k;
            int j = (n < 2) ? 0 : ((n >= L-2) ? 815 : (n-2) >> 2);
            float tq = (n < 2 || n >= L-2) ? 0.f : 0.125f + 0.25f*(float)((n-2) & 3);
            float2 v0 = hvg[j];
            float2 v1 = hvg[j + (j < 815 ? 1 : 0)];
            float hx = v0.x + tq*(v1.x - v0.x);
            float hy = v0.y + tq*(v1.y - v0.y);
            float2 rs = d_res[rbase + n];
            float2 ph = sphm[k];
            sh[k] = make_float2(hx + rs.x*ph.x - rs.y*ph.y,
                                hy + rs.x*ph.y + rs.y*ph.x);
        }
        __syncthreads();
        for (int k = t; k < FCH; k += 256) {
            int n = n0 + k;
            int blk = k / 12;
            int i = k - blk*12;
            const float2* hb = &sh[blk*12];
            float2 acc = {0.f, 0.f};
            #pragma unroll
            for (int j = 0; j < 12; j++) {
                float2 w = sW[i*12 + j], h = hb[j];
                acc.x += w.x*h.x - w.y*h.y;
                acc.y += w.x*h.y + w.y*h.x;
            }
            float2 ph = sphT[k];
            out[(bu*A + a)*L + n] = make_float2(acc.x*ph.x + acc.y*ph.y,
                                                acc.y*ph.x - acc.x*ph.y);
        }
    }
}

extern "C" void kernel_launch(void* const* d_in, const int* in_sizes, int n_in,
                              void* d_out, int out_size) {
    const float* lr = (const float*)d_in[0];
    const float* li = (const float*)d_in[1];
    const int*   cs = (const int*)d_in[2];
    const float* W1 = (const float*)d_in[3];
    const float* b1 = (const float*)d_in[4];
    const float* W2 = (const float*)d_in[5];
    const float* b2 = (const float*)d_in[6];
    float2* out = (float2*)d_out;

    k_dft<<<dim3(B*A, DSPLIT), 512>>>(lr, li, cs);
    k_peak<<<dim3(UP, B), 64>>>(cs);
    k_phasor<<<(NM*L)/256, 256>>>();
    k_havgres<<<dim3(NSP, B*A), 256>>>(lr, li);
    k_feat<<<dim3(NM, 4), 256>>>();
    k_gemm1<<<dim3(GK1, H/64), 256>>>(W1);
    k_mlpw<<<NM, NOUT>>>(b1, W2, b2);
    k_final<<<NM*(A/4)*2, 256>>>(out);
}

// round 17
// speedup vs baseline: 1.1342x; 1.1342x over previous
#include <cuda_runtime.h>
#include <math.h>
#include <stdint.h>

#define B 8
#define UP 8
#define A 32
#define L 3264
#define H 256
#define BSZ 12
#define KCS 12
#define ND 61
#define NPT (UP*ND)        /* 488 */
#define L4 (L/4)           /* 816 */
#define NM (B*UP)          /* 64 */
#define M2L (2*L)          /* 6528 */
#define NOUT 576
#define GK1 34
#define GKLEN (M2L/GK1)    /* 192 */
#define F1 272             /* L = 272 * 12 */
#define F2 12
#define NSP 4              /* n-segments of fused havg+resen */
#define NSEG 816           /* n per segment */
#define DSPLIT 2           /* bin-splits of k_dft */
#define BINS_PER (NPT/DSPLIT)  /* 244 */
#define FCH 1632           /* k_final chunk (divisible by 12) */

// ---------------- scratch (static device globals; no allocation) ----------------
__device__ float2 d_S[B*A][NPT];
__device__ int    d_toff[NM];
__device__ float  d_m[NM];
__device__ float2 d_phm[NM*L];
__device__ float2 d_phT[NM*L];
__device__ float2 d_havg[NM*A*L4];
__device__ float2 d_res[B*A*L];
__device__ float  d_epart[NSP][NM*A];
__device__ float  d_feat[NM*M2L];
__device__ float  d_h1pre[GK1][NM][H];
__device__ float2 d_wm[NM*BSZ*BSZ];

// exact 12th roots of unity
__device__ __constant__ float C12[12] = {
    1.0f,  0.86602540378443864676f,  0.5f, 0.0f, -0.5f, -0.86602540378443864676f,
   -1.0f, -0.86602540378443864676f, -0.5f, 0.0f,  0.5f,  0.86602540378443864676f };
__device__ __constant__ float S12[12] = {
    0.0f,  0.5f,  0.86602540378443864676f, 1.0f,  0.86602540378443864676f,  0.5f,
    0.0f, -0.5f, -0.86602540378443864676f,-1.0f, -0.86602540378443864676f, -0.5f };

// ---------------- K1: fused radix-12 fold + candidate-bin DFT ----------------
// grid (B*A, DSPLIT), block 512.
__global__ void k_dft(const float* __restrict__ lr, const float* __restrict__ li,
                      const int* __restrict__ cs) {
    __shared__ float2 sU[F2][F1+1];   // 26 KB, pad 273
    int ba = blockIdx.x, half = blockIdx.y, t = threadIdx.x;
    if (t < F1) {
        int k1 = t;
        const float* xr = lr + ba*L;
        const float* xi = li + ba*L;
        float vr[F2], vi[F2];
        #pragma unroll
        for (int k2 = 0; k2 < F2; k2++) {
            vr[k2] = xr[k1 + F1*k2];
            vi[k2] = xi[k1 + F1*k2];
        }
        #pragma unroll
        for (int rho = 0; rho < F2; rho++) {
            float ur = 0.f, ui = 0.f;
            #pragma unroll
            for (int k2 = 0; k2 < F2; k2++) {
                float c = C12[(rho*k2) % 12], s = S12[(rho*k2) % 12];
                ur += vr[k2]*c - vi[k2]*s;
                ui += vr[k2]*s + vi[k2]*c;
            }
            sU[rho][k1] = make_float2(ur, ui);
        }
    }
    __syncthreads();
    if (t >= BINS_PER) return;
    int p = half*BINS_PER + t;
    int up = p / ND, dd = p - up*ND;
    int ip = ((KCS - cs[up]) % KCS) * (L / KCS);
    int n = (ip + dd - 30 + L) % L;
    int rho = n % F2;
    const double w0 = 6.283185307179586476925286766559 / (double)L;
    float wx, wy;
    { float th = (float)(w0 * (double)n); sincosf(th, &wy, &wx); }
    float Sx = 0.f, Sy = 0.f;
    for (int c0 = 0; c0 < F1; c0 += 68) {       // resync every 68 steps
        int r = (int)(((long long)c0 * (long long)n) % (long long)L);
        float zx, zy;
        { float th = (float)(w0 * (double)r); sincosf(th, &zy, &zx); }
        #pragma unroll 4
        for (int k1 = c0; k1 < c0 + 68; k1++) {
            float2 u = sU[rho][k1];
            Sx += u.x*zx - u.y*zy;
            Sy += u.x*zy + u.y*zx;
            float nzx = zx*wx - zy*wy;
            float nzy = zx*wy + zy*wx;
            zx = nzx; zy = nzy;
        }
    }
    d_S[ba][p] = make_float2(Sx, Sy);
}

// ---------------- K2: power reduce over a + argmax over d ----------------
__global__ void k_peak(const int* __restrict__ cs) {
    __shared__ float sp[ND];
    int up = blockIdx.x, b = blockIdx.y;
    int tid = threadIdx.x;
    if (tid < ND) {
        int pt = up*ND + tid;
        float s = 0.f;
        for (int a = 0; a < A; a++) {
            float2 v = d_S[b*A + a][pt];
            s += v.x*v.x + v.y*v.y;
        }
        sp[tid] = s;
    }
    __syncthreads();
    if (tid == 0) {
        float best = sp[0]; int bd = 0;
        for (int i = 1; i < ND; i++) if (sp[i] > best) { best = sp[i]; bd = i; }
        int toff = bd - 30;
        int ipk = ((KCS - cs[up]) % KCS) * (L / KCS);
        d_toff[b*UP + up] = toff;
        d_m[b*UP + up]    = (float)(toff + ipk);
    }
}

// accurate sin/cos of a (possibly huge) fp32 phase: double range reduction.
__device__ __forceinline__ float2 expi_big(float th) {
    const double TWO_PI = 6.283185307179586476925286766559;
    const double INV_TWO_PI = 0.15915494309189533576888376337251;
    double x = (double)th;
    double r = x - TWO_PI * rint(x * INV_TWO_PI);
    float2 e; sincosf((float)r, &e.y, &e.x);
    return e;
}

// ---------------- K3: phasor tables (reproduce reference fp32 phase exactly) ----
__global__ void k_phasor() {
    int i = blockIdx.x * blockDim.x + threadIdx.x;   // exactly NM*L
    int bu = i / L, n = i - bu*L;
    const float W = (float)(6.283185307179586476925286766559 / (double)L);
    float nf = (float)n;
    float wm = W * d_m[bu];
    d_phm[i] = expi_big(wm * nf);
    float wt = W * (float)d_toff[bu];
    d_phT[i] = expi_big(wt * nf);
}

// ---------------- K4: fused h_avg + residual + partial energies (coalesced) -----
// Segment s owns n in [s*816, (s+1)*816). Stage 1 computes havg rows
// [j_lo..j_hi] (incl. halo) into smem + global (halo duplicate-writes are
// identical values). Stage 2 iterates n CONTIGUOUSLY so lr/li/phm/res are
// fully coalesced; energy uses |h_res|^2 = |c + res|^2 with c = hi*conj(ph).
__global__ void k_havgres(const float* __restrict__ lr, const float* __restrict__ li) {
    __shared__ float2 sH[UP][207];
    __shared__ float sE[8][9];
    int s  = blockIdx.x;
    int ba = blockIdx.y; int a = ba % A; int b = ba / A;
    int t = threadIdx.x;
    int n_lo = s * NSEG, n_hi = n_lo + NSEG;
    int j_lo = (s == 0) ? 0 : 204*s - 1;
    int j_hi = min(815, 204*(s+1));
    int nrows = j_hi - j_lo + 1;    // <= 206

    // ---- stage 1: havg rows ----
    if (t < nrows) {
        int j = j_lo + t;
        const float4* lr4 = (const float4*)lr;
        const float4* li4 = (const float4*)li;
        float4 xr = lr4[(b*A + a)*L4 + j];
        float4 xi = li4[(b*A + a)*L4 + j];
        #pragma unroll
        for (int up = 0; up < UP; up++) {
            int bu = b*UP + up;
            const float4* ph4 = (const float4*)&d_phm[bu*L + 4*j];
            float4 p01 = ph4[0], p23 = ph4[1];
            float sx, sy;
            sx  = xr.x*p01.x - xi.x*p01.y;  sy  = xr.x*p01.y + xi.x*p01.x;
            sx += xr.y*p01.z - xi.y*p01.w;  sy += xr.y*p01.w + xi.y*p01.z;
            sx += xr.z*p23.x - xi.z*p23.y;  sy += xr.z*p23.y + xi.z*p23.x;
            sx += xr.w*p23.z - xi.w*p23.w;  sy += xr.w*p23.w + xi.w*p23.z;
            float2 hv = make_float2(sx*0.25f, sy*0.25f);
            sH[up][t] = hv;
            d_havg[(bu*A + a)*L4 + j] = hv;
        }
    }
    __syncthreads();

    // ---- stage 2: residual + energies, n-contiguous ----
    float en[UP];
    #pragma unroll
    for (int up = 0; up < UP; up++) en[up] = 0.f;
    int base = (b*A + a)*L;

    for (int n = n_lo + t; n < n_hi; n += 256) {
        int j = (n < 2) ? 0 : ((n >= L-2) ? 815 : (n-2) >> 2);
        float tq = (n < 2 || n >= L-2) ? 0.f : 0.125f + 0.25f*(float)((n-2) & 3);
        int r0 = j - j_lo;
        int r1 = r0 + (j < 815 ? 1 : 0);
        float ax = lr[base + n], ay = li[base + n];
        float cx[UP], cy[UP];
        #pragma unroll
        for (int up = 0; up < UP; up++) {
            float2 v0 = sH[up][r0], v1 = sH[up][r1];
            float hx = v0.x + tq*(v1.x - v0.x);
            float hy = v0.y + tq*(v1.y - v0.y);
            float2 ph = d_phm[(b*UP + up)*L + n];
            cx[up] = hx*ph.x + hy*ph.y;    // Re(hi*conj(ph))
            cy[up] = hy*ph.x - hx*ph.y;    // Im(hi*conj(ph))
            ax -= cx[up];
            ay -= cy[up];
        }
        d_res[base + n] = make_float2(ax, ay);
        #pragma unroll
        for (int up = 0; up < UP; up++) {
            float dx = cx[up] + ax, dy = cy[up] + ay;
            en[up] += dx*dx + dy*dy;
        }
    }
    #pragma unroll
    for (int up = 0; up < UP; up++) {
        float sv = en[up];
        #pragma unroll
        for (int o = 16; o; o >>= 1) sv += __shfl_down_sync(0xffffffffu, sv, o);
        if ((t & 31) == 0) sE[t >> 5][up] = sv;
    }
    __syncthreads();
    if (t < UP) {
        float tot = 0.f;
        #pragma unroll
        for (int w = 0; w < 8; w++) tot += sE[w][t];
        d_epart[s][(b*UP + t)*A + a] = tot;
    }
}

// linear interp on the LOCC grid (matches jnp.interp incl. edge clamping)
__device__ __forceinline__ float2 hinterp(int bu, int a, int n) {
    const float2* row = &d_havg[(bu*A + a)*L4];
    if (n < 2)     return row[0];
    if (n > L-3)   return row[L4-1];
    float x = (float)n - 1.5f;
    int j = (int)(x * 0.25f);
    float t = (x - 4.0f*(float)j) * 0.25f;
    float2 v0 = row[j], v1 = row[j+1];
    return make_float2(v0.x + t*(v1.x - v0.x), v0.y + t*(v1.y - v0.y));
}

__device__ __forceinline__ float2 hres_val(int bu, int a, int n, int b) {
    float2 hi = hinterp(bu, a, n);
    float2 rs = d_res[(b*A + a)*L + n];
    float2 ph = d_phm[bu*L + n];
    return make_float2(hi.x + rs.x*ph.x - rs.y*ph.y,
                       hi.y + rs.x*ph.y + rs.y*ph.x);
}

// ---------------- K7: reduce energy partials, argmax antenna, build features ----
__global__ void k_feat() {
    __shared__ int s_ai;
    int bu = blockIdx.x, b = bu / UP;
    int seg = blockIdx.y;
    if (threadIdx.x == 0) {
        float best = -1.f; int bi = 0;
        for (int a = 0; a < A; a++) {
            float e = 0.f;
            #pragma unroll
            for (int s = 0; s < NSP; s++) e += d_epart[s][bu*A + a];
            if (e > best) { best = e; bi = a; }
        }
        s_ai = bi;
    }
    __syncthreads();
    int a = s_ai;
    int n_lo = seg * (L/4), n_hi = n_lo + (L/4);
    for (int n = n_lo + threadIdx.x; n < n_hi; n += blockDim.x) {
        float2 h = hres_val(bu, a, n, b);
        d_feat[bu*M2L + n]     = h.x;
        d_feat[bu*M2L + L + n] = h.y;
    }
}

// ---------------- K8a: GEMM1 split-K=34  (64x6528)@(6528x256) ----------------
__global__ void k_gemm1(const float* __restrict__ W1) {
    __shared__ float sA[64][8];
    __shared__ float sB[8][64];
    int ks = blockIdx.x, nt = blockIdx.y;
    int t = threadIdx.x;
    int tx = t & 15, ty = t >> 4;
    float acc[4][4] = {};
    int k0 = ks * GKLEN;
    for (int c = 0; c < GKLEN; c += 8) {
        {
            int e = t;       int m = e >> 3, kk = e & 7;
            sA[m][kk] = d_feat[m*M2L + k0 + c + kk];
            e = t + 256;     m = e >> 3;    kk = e & 7;
            sA[m][kk] = d_feat[m*M2L + k0 + c + kk];
        }
        {
            int e = t;       int kk = e >> 6, nn = e & 63;
            sB[kk][nn] = W1[(k0 + c + kk)*H + nt*64 + nn];
            e = t + 256;     kk = e >> 6;    nn = e & 63;
            sB[kk][nn] = W1[(k0 + c + kk)*H + nt*64 + nn];
        }
        __syncthreads();
        #pragma unroll
        for (int kk = 0; kk < 8; kk++) {
            float a0 = sA[ty*4+0][kk], a1 = sA[ty*4+1][kk];
            float a2 = sA[ty*4+2][kk], a3 = sA[ty*4+3][kk];
            float b0 = sB[kk][tx*4+0], b1 = sB[kk][tx*4+1];
            float b2 = sB[kk][tx*4+2], b3 = sB[kk][tx*4+3];
            acc[0][0] += a0*b0; acc[0][1] += a0*b1; acc[0][2] += a0*b2; acc[0][3] += a0*b3;
            acc[1][0] += a1*b0; acc[1][1] += a1*b1; acc[1][2] += a1*b2; acc[1][3] += a1*b3;
            acc[2][0] += a2*b0; acc[2][1] += a2*b1; acc[2][2] += a2*b2; acc[2][3] += a2*b3;
            acc[3][0] += a3*b0; acc[3][1] += a3*b1; acc[3][2] += a3*b2; acc[3][3] += a3*b3;
        }
        __syncthreads();
    }
    #pragma unroll
    for (int r = 0; r < 4; r++)
        #pragma unroll
        for (int cc = 0; cc < 4; cc++)
            d_h1pre[ks][ty*4+r][nt*64 + tx*4+cc] = acc[r][cc];
}

// ---------------- K8b: split-K reduce + relu + GEMM2 + Wmmse (fully fused) ------
__global__ void k_mlpw(const float* __restrict__ b1,
                       const float* __restrict__ W2, const float* __restrict__ b2) {
    __shared__ float sh1[H];
    __shared__ float smlp[NOUT];
    __shared__ float2 RM[12][24];
    __shared__ float2 sAr[144];
    __shared__ float2 sCm[144];
    __shared__ float2 fvec[12];
    int m = blockIdx.x, t = threadIdx.x;   // 576 threads
    if (t < H) {
        float s = b1[t];
        #pragma unroll
        for (int ks = 0; ks < GK1; ks++) s += d_h1pre[ks][m][t];
        sh1[t] = s > 0.f ? s : 0.f;
    }
    __syncthreads();
    {
        float s = b2[t];
        #pragma unroll 4
        for (int k = 0; k < H; k++) s += sh1[k] * W2[k*NOUT + t];
        smlp[t] = s;
    }
    __syncthreads();
    if (t < 144) {
        sCm[t] = make_float2(smlp[t],       smlp[144 + t]);
        sAr[t] = make_float2(smlp[288 + t], smlp[432 + t]);
    }
    __syncthreads();
    if (t < 144) {
        int i = t / 12, j = t % 12;
        float rr = (i == j) ? 1.f : 0.f, ri = 0.f;
        #pragma unroll
        for (int k = 0; k < 12; k++) {
            float2 ax = sAr[i*12 + k], bx = sAr[j*12 + k];
            rr += ax.x*bx.x + ax.y*bx.y;
            ri += ax.y*bx.x - ax.x*bx.y;
        }
        RM[i][j]      = make_float2(rr, ri);
        RM[i][12 + j] = make_float2(i == j ? 1.f : 0.f, 0.f);
    }
    __syncthreads();
    int r = t / 24, c = t % 24;
    for (int p = 0; p < 12; p++) {
        if (t < 12) fvec[t] = RM[t][p];
        __syncthreads();
        if (t < 288 && r == p) {
            float2 pv = fvec[p];
            float den = pv.x*pv.x + pv.y*pv.y;
            float2 pinv = make_float2(pv.x/den, -pv.y/den);
            float2 v = RM[p][c];
            RM[p][c] = make_float2(v.x*pinv.x - v.y*pinv.y, v.x*pinv.y + v.y*pinv.x);
        }
        __syncthreads();
        if (t < 288 && r != p) {
            float2 f = fvec[r], pr = RM[p][c], v = RM[r][c];
            v.x -= f.x*pr.x - f.y*pr.y;
            v.y -= f.x*pr.y + f.y*pr.x;
            RM[r][c] = v;
        }
        __syncthreads();
    }
    if (t < 144) {
        int i = t / 12, j = t % 12;
        float wr = 0.f, wi = 0.f;
        #pragma unroll
        for (int k = 0; k < 12; k++) {
            float2 cm = sCm[i*12 + k], iv = RM[k][12 + j];
            wr += cm.x*iv.x - cm.y*iv.y;
            wi += cm.x*iv.y + cm.y*iv.x;
        }
        d_wm[m*144 + t] = make_float2(wr, wi);
    }
}

// ---------------- K9: Wmmse filter + derotate; chunk index in grid ------------
__global__ void k_final(float2* __restrict__ out) {
    __shared__ float2 sW[144];
    __shared__ float2 sh[FCH];
    int id = blockIdx.x;
    int c  = id & 1;
    int ba = id >> 1;
    int a  = ba % A;
    int bu = ba / A;
    int b  = bu / UP;
    int t = threadIdx.x;           // 256
    if (t < 144) sW[t] = d_wm[bu*144 + t];
    const float2* hvg = &d_havg[(bu*A + a)*L4];
    int rbase = (b*A + a)*L;
    int n0 = c * FCH;
    for (int k = t; k < FCH; k += 256) {
        int n = n0 + k;
        int j = (n < 2) ? 0 : ((n >= L-2) ? 815 : (n-2) >> 2);
        float tq = (n < 2 || n >= L-2) ? 0.f : 0.125f + 0.25f*(float)((n-2) & 3);
        float2 v0 = hvg[j];
        float2 v1 = hvg[j + (j < 815 ? 1 : 0)];
        float hx = v0.x + tq*(v1.x - v0.x);
        float hy = v0.y + tq*(v1.y - v0.y);
        float2 rs = d_res[rbase + n];
        float2 ph = d_phm[bu*L + n];
        sh[k] = make_float2(hx + rs.x*ph.x - rs.y*ph.y,
                            hy + rs.x*ph.y + rs.y*ph.x);
    }
    __syncthreads();
    for (int k = t; k < FCH; k += 256) {
        int n = n0 + k;
        int blk = k / 12;
        int i = k - blk*12;
        const float2* hb = &sh[blk*12];
        float2 acc = {0.f, 0.f};
        #pragma unroll
        for (int j = 0; j < 12; j++) {
            float2 w = sW[i*12 + j], h = hb[j];
            acc.x += w.x*h.x - w.y*h.y;
            acc.y += w.x*h.y + w.y*h.x;
        }
        float2 ph = d_phT[bu*L + n];
        out[(bu*A + a)*L + n] = make_float2(acc.x*ph.x + acc.y*ph.y,
                                            acc.y*ph.x - acc.x*ph.y);
    }
}

extern "C" void kernel_launch(void* const* d_in, const int* in_sizes, int n_in,
                              void* d_out, int out_size) {
    const float* lr = (const float*)d_in[0];
    const float* li = (const float*)d_in[1];
    const int*   cs = (const int*)d_in[2];
    const float* W1 = (const float*)d_in[3];
    const float* b1 = (const float*)d_in[4];
    const float* W2 = (const float*)d_in[5];
    const float* b2 = (const float*)d_in[6];
    float2* out = (float2*)d_out;

    k_dft<<<dim3(B*A, DSPLIT), 512>>>(lr, li, cs);
    k_peak<<<dim3(UP, B), 64>>>(cs);
    k_phasor<<<(NM*L)/256, 256>>>();
    k_havgres<<<dim3(NSP, B*A), 256>>>(lr, li);
    k_feat<<<dim3(NM, 4), 256>>>();
    k_gemm1<<<dim3(GK1, H/64), 256>>>(W1);
    k_mlpw<<<NM, NOUT>>>(b1, W2, b2);
    k_final<<<NM*A*2, 256>>>(out);
}